// round 6
// baseline (speedup 1.0000x reference)
#include <cuda_runtime.h>

// GCMConv: gauge-covariant convolution on 8x8x16x16 lattice.
// x: (1, 16384, 8, 3, 3, 2) float32  [channels: 4 gauge links U_a, 4 fields w_c]
// weight: (4, 9, 33) float32
// out: (1, 16384, 8, 3, 3, 2): [U (copied), w_out]
//
// Conj-hoisted M-form with packed f32x2 FMA:
//   M_v = Mp_v + Mq_v^dag + c3_v I,  Mp_v = sum_k c1_{vk} T_k,  Mq_v = sum_k c2_{vk} T_k
//   (c1,c2 real -> both accumulate from the SAME packed (re,im) T stream)
//   w_out[u] = sum_{v<4} w_v @ M_v + sum_{v=4..7} w_{v-4}^dag @ M_v + M_8
// 3 passes of 3 v each keep Mp/Mq register footprint at 108 regs.

#define NS 16384

// Scratch, float2 (re,im), [(e)*NS + site]:
//  e = k*9 + m        (k=0..15): T_k[m],  m = row*3+col
//  e = 144 + c*9 + m  (c=0..3) : own-site w_c[m]
__device__ float2 g_T[180 * NS];

typedef unsigned long long ull;

__device__ __forceinline__ ull pk2(float lo, float hi) {
    ull r;
    asm("mov.b64 %0, {%1, %2};" : "=l"(r) : "f"(lo), "f"(hi));
    return r;
}
__device__ __forceinline__ void upk2(float& lo, float& hi, ull v) {
    asm("mov.b64 {%0, %1}, %2;" : "=f"(lo), "=f"(hi) : "l"(v));
}
__device__ __forceinline__ ull fma2(ull a, ull b, ull c) {
    ull d;
    asm("fma.rn.f32x2 %0, %1, %2, %3;" : "=l"(d) : "l"(a), "l"(b), "l"(c));
    return d;
}

__global__ __launch_bounds__(256) void transport_kernel(const float* __restrict__ x) {
    int g = blockIdx.x * 256 + threadIdx.x;   // 0 .. 4*NS-1
    int site = g & (NS - 1);
    int a = g >> 14;                           // axis 0..3

    // periodic +1 neighbor; dims (8,8,16,16), strides (2048,256,16,1)
    int d3 = site & 15, d2 = (site >> 4) & 15, d1 = (site >> 8) & 7, d0 = (site >> 11) & 7;
    int nbr;
    if (a == 0)      nbr = site + ((((d0 + 1) & 7) - d0) << 11);
    else if (a == 1) nbr = site + ((((d1 + 1) & 7) - d1) << 8);
    else if (a == 2) nbr = site + ((((d2 + 1) & 15) - d2) << 4);
    else             nbr = site + (((d3 + 1) & 15) - d3);

    float Ur[3][3], Ui[3][3];
    {
        const float2* up = (const float2*)(x + site * 144 + a * 18);
#pragma unroll
        for (int m = 0; m < 9; m++) {
            float2 t = up[m];
            Ur[m / 3][m % 3] = t.x;
            Ui[m / 3][m % 3] = t.y;
        }
    }

#pragma unroll
    for (int c = 0; c < 4; c++) {
        float Wr[3][3], Wi[3][3];
        const float2* wp = (const float2*)(x + nbr * 144 + (4 + c) * 18);
#pragma unroll
        for (int m = 0; m < 9; m++) {
            float2 t = wp[m];
            Wr[m / 3][m % 3] = t.x;
            Wi[m / 3][m % 3] = t.y;
        }
        // t1 = U @ W
        float t1r[3][3], t1i[3][3];
#pragma unroll
        for (int i = 0; i < 3; i++)
#pragma unroll
            for (int kk = 0; kk < 3; kk++) {
                float cr = 0.f, ci = 0.f;
#pragma unroll
                for (int j = 0; j < 3; j++) {
                    cr += Ur[i][j] * Wr[j][kk] - Ui[i][j] * Wi[j][kk];
                    ci += Ur[i][j] * Wi[j][kk] + Ui[i][j] * Wr[j][kk];
                }
                t1r[i][kk] = cr;
                t1i[i][kk] = ci;
            }
        // T = t1 @ U^dag
        int ebase = (a * 4 + c) * 9;
#pragma unroll
        for (int i = 0; i < 3; i++)
#pragma unroll
            for (int kk = 0; kk < 3; kk++) {
                float cr = 0.f, ci = 0.f;
#pragma unroll
                for (int j = 0; j < 3; j++) {
                    float br = Ur[kk][j], bi = -Ui[kk][j];
                    cr += t1r[i][j] * br - t1i[i][j] * bi;
                    ci += t1r[i][j] * bi + t1i[i][j] * br;
                }
                g_T[(ebase + i * 3 + kk) * NS + site] = make_float2(cr, ci);
            }
    }

    // own-site field: thread (site, a) copies channel c = a
    {
        const float2* wp = (const float2*)(x + site * 144 + (4 + a) * 18);
#pragma unroll
        for (int m = 0; m < 9; m++)
            g_T[(144 + a * 9 + m) * NS + site] = wp[m];
    }
}

__global__ __launch_bounds__(64, 6) void contract_kernel(const float* __restrict__ x,
                                                         const float* __restrict__ weight,
                                                         float* __restrict__ out) {
    __shared__ ull wt2[297];   // [w*9 + v] = (c, c) packed, c = weight[u, v, w]

    int g = blockIdx.x * 64 + threadIdx.x;
    int site = g & (NS - 1);
    int u = g >> 14;  // whole block shares one u

    for (int s = threadIdx.x; s < 297; s += 64) {
        int v = s / 33, w = s % 33;
        float c = weight[u * 297 + s];
        wt2[w * 9 + v] = pk2(c, c);
    }
    __syncthreads();

    const ull* gt = reinterpret_cast<const ull*>(g_T);

    // copy gauge link channel u to output
    {
        const ull* src = reinterpret_cast<const ull*>(x + site * 144 + u * 18);
        ull* dst = reinterpret_cast<ull*>(out + site * 144 + u * 18);
#pragma unroll
        for (int m = 0; m < 9; m++) dst[m] = src[m];
    }

    float accr[3][3], acci[3][3];
#pragma unroll
    for (int i = 0; i < 3; i++)
#pragma unroll
        for (int j = 0; j < 3; j++) { accr[i][j] = 0.f; acci[i][j] = 0.f; }

    // 3 passes over v-groups {0,1,2}, {3,4,5}, {6,7,8}
#pragma unroll
    for (int vb = 0; vb < 9; vb += 3) {
        ull Mp[3][9], Mq[3][9];
#pragma unroll
        for (int t = 0; t < 3; t++)
#pragma unroll
            for (int m = 0; m < 9; m++) { Mp[t][m] = 0ull; Mq[t][m] = 0ull; }

        // double-buffered stream over T_k
        ull Tb[2][9];
#pragma unroll
        for (int m = 0; m < 9; m++) Tb[0][m] = gt[m * NS + site];

#pragma unroll 2
        for (int k = 0; k < 16; k++) {
            int cur = k & 1;
            if (k < 15) {
#pragma unroll
                for (int m = 0; m < 9; m++)
                    Tb[cur ^ 1][m] = gt[((k + 1) * 9 + m) * NS + site];
            }
#pragma unroll
            for (int t = 0; t < 3; t++) {
                ull a1 = wt2[k * 9 + vb + t];
                ull a2 = wt2[(16 + k) * 9 + vb + t];
#pragma unroll
                for (int m = 0; m < 9; m++) {
                    Mp[t][m] = fma2(a1, Tb[cur][m], Mp[t][m]);
                    Mq[t][m] = fma2(a2, Tb[cur][m], Mq[t][m]);
                }
            }
        }

        // epilogue: N_v = Mp_v + Mq_v^dag + c3_v I ; acc += A_v @ N_v
#pragma unroll
        for (int t = 0; t < 3; t++) {
            int v = vb + t;
            float c3, dummy;
            upk2(c3, dummy, wt2[32 * 9 + v]);

            float nr[3][3], ni[3][3];
#pragma unroll
            for (int i = 0; i < 3; i++)
#pragma unroll
                for (int j = 0; j < 3; j++) {
                    float pr, pi, qr, qi;
                    upk2(pr, pi, Mp[t][i * 3 + j]);
                    upk2(qr, qi, Mq[t][j * 3 + i]);
                    nr[i][j] = pr + qr + ((i == j) ? c3 : 0.f);
                    ni[i][j] = pi - qi;
                }

            if (v == 8) {
#pragma unroll
                for (int i = 0; i < 3; i++)
#pragma unroll
                    for (int j = 0; j < 3; j++) { accr[i][j] += nr[i][j]; acci[i][j] += ni[i][j]; }
            } else {
                int c = (v < 4) ? v : (v - 4);
                float wr[3][3], wi[3][3];
#pragma unroll
                for (int m = 0; m < 9; m++) {
                    float2 t2 = ((const float2*)g_T)[(144 + c * 9 + m) * NS + site];
                    wr[m / 3][m % 3] = t2.x;
                    wi[m / 3][m % 3] = t2.y;
                }
                if (v < 4) {
                    // acc += w_c @ N
#pragma unroll
                    for (int i = 0; i < 3; i++)
#pragma unroll
                        for (int kk = 0; kk < 3; kk++) {
                            float cr = accr[i][kk], ci = acci[i][kk];
#pragma unroll
                            for (int j = 0; j < 3; j++) {
                                cr += wr[i][j] * nr[j][kk] - wi[i][j] * ni[j][kk];
                                ci += wr[i][j] * ni[j][kk] + wi[i][j] * nr[j][kk];
                            }
                            accr[i][kk] = cr; acci[i][kk] = ci;
                        }
                } else {
                    // acc += w_c^dag @ N : conj(w[j][i]) * N[j][kk]
#pragma unroll
                    for (int i = 0; i < 3; i++)
#pragma unroll
                        for (int kk = 0; kk < 3; kk++) {
                            float cr = accr[i][kk], ci = acci[i][kk];
#pragma unroll
                            for (int j = 0; j < 3; j++) {
                                cr += wr[j][i] * nr[j][kk] + wi[j][i] * ni[j][kk];
                                ci += wr[j][i] * ni[j][kk] - wi[j][i] * nr[j][kk];
                            }
                            accr[i][kk] = cr; acci[i][kk] = ci;
                        }
                }
            }
        }
    }

    float2* dst = (float2*)(out + site * 144 + (4 + u) * 18);
#pragma unroll
    for (int i = 0; i < 3; i++)
#pragma unroll
        for (int j = 0; j < 3; j++)
            dst[i * 3 + j] = make_float2(accr[i][j], acci[i][j]);
}

extern "C" void kernel_launch(void* const* d_in, const int* in_sizes, int n_in,
                              void* d_out, int out_size) {
    const float* x = (const float*)d_in[0];
    const float* weight = (const float*)d_in[1];
    float* out = (float*)d_out;

    transport_kernel<<<4 * NS / 256, 256>>>(x);
    contract_kernel<<<4 * NS / 64, 64>>>(x, weight, out);
}